// round 9
// baseline (speedup 1.0000x reference)
#include <cuda_runtime.h>

// ---------------------------------------------------------------------------
// TensoRF slim renderer, v9 — fully precomputed per-corner records.
//  prep: combined 128B texels g_tex[i][HW][32ch] (ch0-7 density, basis
//        weights folded into the LINE texture; ch8-31 appearance).
//  render (block=ray, 256 thr, warp = 32 samples, dynamic smem):
//    setup (thread = point): per (plane, corner) write a 16B record
//      (corner texel idx, packed tap idxs, s0, s1) with the bilinear corner
//      weight wc folded into the tap-lerp scalars s0/s1.
//    main: per point per plane: 1 LDS.128 + 3 LDG + packed f32x2 math.
//      rows 0-2 via register appw (app lanes); sigma via add2 (density lanes).
//      6-shuffle butterfly reduce -> (q0,q1,q2,sigma) per point.
//    then alpha(-expm1) + smem product scan -> weights -> rgb reduce.
// ---------------------------------------------------------------------------

#define MAXG  320
#define MAXHW (MAXG * MAXG)

__device__ float4 g_tex[3ull * MAXHW * 8];   // [i][p][8 float4] texel = 128B
__device__ float4 g_ltex[3 * MAXG * 8];      // [i][g][8 float4]

typedef unsigned long long ull;

__device__ __forceinline__ ull f2pk(float a, float b) {
    ull r; asm("mov.b64 %0,{%1,%2};" : "=l"(r) : "f"(a), "f"(b)); return r;
}
__device__ __forceinline__ float2 f2un(ull v) {
    float2 r; asm("mov.b64 {%0,%1},%2;" : "=f"(r.x), "=f"(r.y) : "l"(v)); return r;
}
__device__ __forceinline__ ull fma2(ull a, ull b, ull c) {
    ull r; asm("fma.rn.f32x2 %0,%1,%2,%3;" : "=l"(r) : "l"(a), "l"(b), "l"(c)); return r;
}
__device__ __forceinline__ ull mul2(ull a, ull b) {
    ull r; asm("mul.rn.f32x2 %0,%1,%2;" : "=l"(r) : "l"(a), "l"(b)); return r;
}
__device__ __forceinline__ ull add2(ull a, ull b) {
    ull r; asm("add.rn.f32x2 %0,%1,%2;" : "=l"(r) : "l"(a), "l"(b)); return r;
}

// ---------------- prep: interleave channels into 128B texels ----------------
__global__ void prep_kernel(const float* __restrict__ dp, const float* __restrict__ ap,
                            const float* __restrict__ dl, const float* __restrict__ al,
                            const float* __restrict__ denw, int G) {
    __shared__ float tile[32][129];
    int HW  = G * G;
    int ntp = (HW + 127) >> 7;
    int ntl = (G + 127) >> 7;
    int b = blockIdx.x;
    if (b < 3 * ntp) {
        int i = b / ntp, t = b - i * ntp;
        int p0 = t << 7;
        int np = min(128, HW - p0);
        for (int idx = threadIdx.x; idx < 32 * 128; idx += blockDim.x) {
            int ch = idx >> 7, p = idx & 127;
            float v = 0.f;
            if (p < np)
                v = (ch < 8) ? dp[(size_t)(i * 8 + ch) * HW + p0 + p]
                             : ap[(size_t)(i * 24 + ch - 8) * HW + p0 + p];
            tile[ch][p] = v;
        }
        __syncthreads();
        float* dst = (float*)(g_tex + ((size_t)i * MAXHW + p0) * 8);
        for (int idx = threadIdx.x; idx < np * 32; idx += blockDim.x) {
            int p = idx >> 5, ch = idx & 31;
            dst[idx] = tile[ch][p];
        }
    } else {
        b -= 3 * ntp;
        int i = b / ntl, t = b - i * ntl;
        int g0 = t << 7;
        int ng = min(128, G - g0);
        for (int idx = threadIdx.x; idx < 32 * 128; idx += blockDim.x) {
            int ch = idx >> 7, g = idx & 127;
            float v = 0.f;
            if (g < ng) {
                if (ch < 8) v = dl[(i * 8 + ch) * G + g0 + g] * denw[i * 8 + ch];
                else        v = al[(i * 24 + ch - 8) * G + g0 + g];
            }
            tile[ch][g] = v;
        }
        __syncthreads();
        float* dst = (float*)(g_ltex + ((size_t)i * MAXG + g0) * 8);
        for (int idx = threadIdx.x; idx < ng * 32; idx += blockDim.x) {
            int g = idx >> 5, ch = idx & 31;
            dst[idx] = tile[ch][g];
        }
    }
}

// ---------------- render ----------------
struct S1D { int i0, i1; float w; };

__device__ __forceinline__ S1D samp1d(float c, int G) {
    float f  = (c + 1.0f) * 0.5f * (float)(G - 1);
    float ff = floorf(f);
    S1D r;
    r.w = f - ff;                 // frac from UNclipped floor (matches ref)
    int i0 = (int)ff;
    i0 = min(max(i0, 0), G - 1);
    r.i0 = i0;
    r.i1 = min(i0 + 1, G - 1);
    return r;
}

// dynamic smem layout (floats):
//  s_pp  : 256*12 float4  (49152 B)
//  s_out : 1024, s_z: 256, s_A: 256, s_B: 256, s_part: 24
#define SMEM_BYTES (49152 + (1024 + 256 + 256 + 256 + 24) * 4)

__global__ __launch_bounds__(256, 3)
void render_kernel(const float* __restrict__ xyz,
                   const float* __restrict__ zvals,
                   const float* __restrict__ appw,
                   const float* __restrict__ aabb,
                   float* __restrict__ out,
                   int Ns, int G) {
    extern __shared__ float4 dsm[];
    float4* s_pp   = dsm;                       // [pt][plane][corner] 16B rec
    float*  s_out  = (float*)(dsm + 256 * 12);  // q0,q1,q2,sigma per point
    float*  s_z    = s_out + 1024;
    float*  s_A    = s_z + 256;
    float*  s_B    = s_A + 256;
    float*  s_part = s_B + 256;

    const int r      = blockIdx.x;
    const int tid    = threadIdx.x;
    const int lane   = tid & 31;
    const int wrp    = tid >> 5;
    const int corner = lane >> 3;       // 0..3
    const int slot   = lane & 7;        // 0..7 (f4 index within texel)
    const bool isApp = (slot >= 2);

    // packed appw rows 0-2 (zeros on density lanes)
    ull WA[3][3], WB[3][3];
#pragma unroll
    for (int rr = 0; rr < 3; rr++)
#pragma unroll
        for (int i = 0; i < 3; i++) {
            if (isApp) {
                float4 w = *(const float4*)(appw + rr * 72 + i * 24 + (slot - 2) * 4);
                WA[rr][i] = f2pk(w.x, w.y);
                WB[rr][i] = f2pk(w.z, w.w);
            } else {
                WA[rr][i] = 0ull; WB[rr][i] = 0ull;
            }
        }

    // ---------- setup: per-point per-corner records ----------
    {
        size_t base = ((size_t)r * Ns + tid) * 3;
        float nc[3];
#pragma unroll
        for (int k = 0; k < 3; k++) {
            float lo = aabb[k], hi = aabb[3 + k];
            nc[k] = (xyz[base + k] - lo) * (2.0f / (hi - lo)) - 1.0f;
        }
        s_z[tid] = zvals[(size_t)r * Ns + tid];

        const int MA[3] = {0, 0, 1}, MB[3] = {1, 2, 2}, MV[3] = {2, 1, 0};
#pragma unroll
        for (int i = 0; i < 3; i++) {
            S1D sx = samp1d(nc[MA[i]], G);
            S1D sy = samp1d(nc[MB[i]], G);
            S1D st = samp1d(nc[MV[i]], G);
            int bu  = i * (MAXHW * 8) + (sy.i0 * G + sx.i0) * 8;  // f4 units
            int dxu = (sx.i1 - sx.i0) * 8;
            int dyu = (sy.i1 - sy.i0) * G * 8;
            int T   = (i * (MAXG * 8) + st.i0 * 8)
                    | ((i * (MAXG * 8) + st.i1 * 8) << 16);
            float wx1 = sx.w, wx0 = 1.f - sx.w;
            float wy1 = sy.w, wy0 = 1.f - sy.w;
            int   cu[4]  = {bu, bu + dxu, bu + dyu, bu + dxu + dyu};
            float wcs[4] = {wx0 * wy0, wx1 * wy0, wx0 * wy1, wx1 * wy1};
#pragma unroll
            for (int c = 0; c < 4; c++) {
                float s1 = wcs[c] * st.w;
                float s0 = wcs[c] - s1;
                s_pp[tid * 12 + i * 4 + c] = make_float4(
                    __int_as_float(cu[c]), __int_as_float(T), s0, s1);
            }
        }
    }
    __syncthreads();

    const ulonglong2* tbp = (const ulonglong2*)g_tex  + slot;
    const ulonglong2* lbp = (const ulonglong2*)g_ltex + slot;
    const float4*     ppc = s_pp + corner;     // lane's corner folded in

    // ---------- main pass: 32 points per warp ----------
    const int p0 = wrp << 5;
    for (int it = 0; it < 32; it++) {
        int p = p0 + it;
        ull acc0 = 0ull, acc1 = 0ull, acc2 = 0ull, sacc = 0ull;
#pragma unroll
        for (int i = 0; i < 3; i++) {
            float4 R = ppc[p * 12 + i * 4];
            int coff = __float_as_int(R.x);
            int T    = __float_as_int(R.y);
            ull s0p  = f2pk(R.z, R.z);
            ull s1p  = f2pk(R.w, R.w);

            ulonglong2 tex = __ldg(tbp + coff);
            ulonglong2 l0  = __ldg(lbp + (T & 0xFFFF));
            ulonglong2 l1  = __ldg(lbp + ((unsigned)T >> 16));

            ull gA = mul2(tex.x, fma2(l1.x, s1p, mul2(l0.x, s0p)));
            ull gB = mul2(tex.y, fma2(l1.y, s1p, mul2(l0.y, s0p)));

            acc0 = fma2(gB, WB[0][i], fma2(gA, WA[0][i], acc0));
            acc1 = fma2(gB, WB[1][i], fma2(gA, WA[1][i], acc1));
            acc2 = fma2(gB, WB[2][i], fma2(gA, WA[2][i], acc2));
            sacc = add2(sacc, add2(gA, gB));
        }
        float2 a0 = f2un(acc0);
        float2 a1 = f2un(acc1);
        float2 a2 = f2un(acc2);
        float2 a3 = f2un(sacc);
        float v0 = a0.x + a0.y;
        float v1 = a1.x + a1.y;
        float v2 = a2.x + a2.y;
        float v3 = isApp ? 0.f : (a3.x + a3.y);   // sigma: density lanes only

        // 6-shuffle 4-output butterfly reduce; row r lands on lanes (lane&3)==r
        const int b0 = lane & 1;
        const int b1 = lane & 2;
        float s1v = b0 ? v0 : v1;
        float r1  = __shfl_xor_sync(0xffffffffu, s1v, 1);
        float u0  = (b0 ? v1 : v0) + r1;           // row b0
        float s2v = b0 ? v2 : v3;
        float r2  = __shfl_xor_sync(0xffffffffu, s2v, 1);
        float u1  = (b0 ? v3 : v2) + r2;           // row 2+b0
        float s3v = b1 ? u0 : u1;
        float r3  = __shfl_xor_sync(0xffffffffu, s3v, 2);
        float wv  = (b1 ? u1 : u0) + r3;           // row lane&3
        wv += __shfl_xor_sync(0xffffffffu, wv, 4);
        wv += __shfl_xor_sync(0xffffffffu, wv, 8);
        wv += __shfl_xor_sync(0xffffffffu, wv, 16);
        if (lane < 4) s_out[p * 4 + lane] = wv;
    }
    __syncthreads();

    // ---------- alpha + transmittance scan -> weights ----------
    float w;
    {
        float sfeat = s_out[tid * 4 + 3] - 10.0f;
        float sigma = (sfeat > 15.0f) ? sfeat : log1pf(expf(sfeat));
        float dist  = (tid < Ns - 1) ? (s_z[tid + 1] - s_z[tid])
                                     : (s_z[Ns - 1] - s_z[Ns - 2]);
        float alpha = -expm1f(-sigma * (dist * 25.0f));
        s_A[tid] = 1.0f - alpha + 1e-10f;
        __syncthreads();
        float* cur = s_A;
        float* nxt = s_B;
        for (int off = 1; off < Ns; off <<= 1) {
            float v = cur[tid];
            if (tid >= off) v *= cur[tid - off];
            nxt[tid] = v;
            __syncthreads();
            float* tmp = cur; cur = nxt; nxt = tmp;
        }
        float T = (tid == 0) ? 1.0f : cur[tid - 1];
        w = alpha * T;
    }

    // ---------- weighted rgb sum ----------
    float q0 = w * s_out[tid * 4 + 0];
    float q1 = w * s_out[tid * 4 + 1];
    float q2 = w * s_out[tid * 4 + 2];
#pragma unroll
    for (int m = 16; m > 0; m >>= 1) {
        q0 += __shfl_xor_sync(0xffffffffu, q0, m);
        q1 += __shfl_xor_sync(0xffffffffu, q1, m);
        q2 += __shfl_xor_sync(0xffffffffu, q2, m);
    }
    if (lane == 0) {
        s_part[wrp * 3 + 0] = q0;
        s_part[wrp * 3 + 1] = q1;
        s_part[wrp * 3 + 2] = q2;
    }
    __syncthreads();
    if (tid < 3) {
        float sum = 0.f;
#pragma unroll
        for (int ww = 0; ww < 8; ww++) sum += s_part[ww * 3 + tid];
        out[r * 3 + tid] = sum;
    }
}

extern "C" void kernel_launch(void* const* d_in, const int* in_sizes, int n_in,
                              void* d_out, int out_size) {
    const float* xyz   = (const float*)d_in[0];
    const float* zvals = (const float*)d_in[2];
    const float* dp    = (const float*)d_in[3];
    const float* dl    = (const float*)d_in[4];
    const float* ap    = (const float*)d_in[5];
    const float* al    = (const float*)d_in[6];
    const float* denw  = (const float*)d_in[7];
    const float* appw  = (const float*)d_in[8];
    const float* aabb  = (const float*)d_in[9];

    int Nr = in_sizes[1] / 3;
    int Ns = in_sizes[2] / Nr;
    int G  = in_sizes[4] / 24;
    int HW = G * G;

    cudaFuncSetAttribute(render_kernel,
                         cudaFuncAttributeMaxDynamicSharedMemorySize, SMEM_BYTES);

    int ntp = (HW + 127) / 128;
    int ntl = (G + 127) / 128;
    prep_kernel<<<3 * ntp + 3 * ntl, 256>>>(dp, ap, dl, al, denw, G);
    render_kernel<<<Nr, Ns, SMEM_BYTES>>>(xyz, zvals, appw, aabb,
                                          (float*)d_out, Ns, G);
}